// round 2
// baseline (speedup 1.0000x reference)
#include <cuda_runtime.h>
#include <math.h>

#define Bz   8
#define Sz   512
#define Dm   512
#define Hn   8
#define DKh  64
#define Lz   6
#define DFFz 2048
#define OUTz 1000
#define NEGV (-1e9f)

// ---------------- scratch (device globals: allowed) ----------------
__device__ float g_e[Bz*Sz*Dm];
__device__ float g_q[Bz*Sz*Dm];
__device__ float g_k[Bz*Sz*Dm];
__device__ float g_v[Bz*Sz*Dm];
__device__ float g_sc[(size_t)Bz*Hn*Sz*Sz];
__device__ float g_attn[Bz*Sz*Dm];
__device__ float g_h[Bz*Sz*DFFz];
__device__ float g_t[Bz*Sz*Dm];
__device__ float g_d[Bz*Dm];
__device__ float g_dq[Bz*Dm];
__device__ float g_dt[Bz*Dm];
__device__ float g_dh[Bz*DFFz];

// ---------------- embedding + positional encoding ----------------
__global__ void embed_enc(const int* __restrict__ x, const float* __restrict__ emb,
                          float* __restrict__ e) {
    int idx = blockIdx.x*blockDim.x + threadIdx.x;
    if (idx >= Bz*Sz*Dm) return;
    int d  = idx % Dm;
    int bs = idx / Dm;
    int s  = bs % Sz;
    int tok = x[bs];
    double div = exp(-(double)((d >> 1) << 1) * (log(10000.0) / (double)Dm));
    double arg = (double)s * div;
    float pe = (d & 1) ? (float)cos(arg) : (float)sin(arg);
    e[idx] = emb[tok*Dm + d] * 22.627416997969522f + pe;
}

__global__ void embed_dec(const int* __restrict__ tgt, const float* __restrict__ emb,
                          float* __restrict__ o) {
    int idx = blockIdx.x*blockDim.x + threadIdx.x;
    if (idx >= Bz*Dm) return;
    int d = idx % Dm;
    int b = idx / Dm;
    float pe = (d & 1) ? 1.f : 0.f;   // PE[0]: sin(0)=0, cos(0)=1
    o[idx] = emb[tgt[b]*Dm + d] * 22.627416997969522f + pe;
}

// ---------------- big SGEMM: C[M,N] = A[M,K] @ W[K,N] + bias (+relu) ----------
// BM=BN=64, BK=16, 256 threads, 4x4 per thread. M,N,K multiples of 64/16.
template<int RELU>
__global__ void sgemm(const float* __restrict__ A, const float* __restrict__ W,
                      const float* __restrict__ bias, float* __restrict__ C,
                      int M, int N, int K) {
    __shared__ float As[16][68];
    __shared__ float Bs[16][64];
    int tid = threadIdx.x;
    int m0 = blockIdx.y * 64, n0 = blockIdx.x * 64;
    int ty = tid >> 4, tx = tid & 15;
    int ar = tid >> 2, ak = (tid & 3) * 4;
    int bk = tid >> 4, bn = (tid & 15) * 4;
    float acc[4][4] = {};
    for (int k0 = 0; k0 < K; k0 += 16) {
        float4 a4 = *(const float4*)&A[(size_t)(m0 + ar)*K + k0 + ak];
        float4 b4 = *(const float4*)&W[(size_t)(k0 + bk)*N + n0 + bn];
        As[ak+0][ar] = a4.x; As[ak+1][ar] = a4.y;
        As[ak+2][ar] = a4.z; As[ak+3][ar] = a4.w;
        *(float4*)&Bs[bk][bn] = b4;
        __syncthreads();
#pragma unroll
        for (int k = 0; k < 16; k++) {
            float4 av = *(float4*)&As[k][ty*4];
            float4 bv = *(float4*)&Bs[k][tx*4];
            acc[0][0] += av.x*bv.x; acc[0][1] += av.x*bv.y; acc[0][2] += av.x*bv.z; acc[0][3] += av.x*bv.w;
            acc[1][0] += av.y*bv.x; acc[1][1] += av.y*bv.y; acc[1][2] += av.y*bv.z; acc[1][3] += av.y*bv.w;
            acc[2][0] += av.z*bv.x; acc[2][1] += av.z*bv.y; acc[2][2] += av.z*bv.z; acc[2][3] += av.z*bv.w;
            acc[3][0] += av.w*bv.x; acc[3][1] += av.w*bv.y; acc[3][2] += av.w*bv.z; acc[3][3] += av.w*bv.w;
        }
        __syncthreads();
    }
#pragma unroll
    for (int i = 0; i < 4; i++) {
        int m = m0 + ty*4 + i;
#pragma unroll
        for (int j = 0; j < 4; j++) {
            int n = n0 + tx*4 + j;
            float val = acc[i][j] + bias[n];
            if (RELU) val = fmaxf(val, 0.f);
            C[(size_t)m*N + n] = val;
        }
    }
}

// ---------------- attention scores: S = Q K^T / 8 with quirky mask ----------
// grid (ktile=8, qtile=8, bh=64), block 256
__global__ void attn_scores(const float* __restrict__ q, const float* __restrict__ k,
                            float* __restrict__ sc) {
    __shared__ float Qs[64][68];  // [d][q]
    __shared__ float Ks[64][68];  // [d][k]
    int bh = blockIdx.z, b = bh >> 3, h = bh & 7;
    int q0 = blockIdx.y * 64, k0 = blockIdx.x * 64;
    int tid = threadIdx.x;
#pragma unroll
    for (int it = 0; it < 4; it++) {
        int idx = tid + it*256;
        int r = idx >> 4;
        int c = (idx & 15) * 4;
        float4 a = *(const float4*)&q[(size_t)(b*Sz + q0 + r)*Dm + h*DKh + c];
        Qs[c+0][r] = a.x; Qs[c+1][r] = a.y; Qs[c+2][r] = a.z; Qs[c+3][r] = a.w;
        float4 bb = *(const float4*)&k[(size_t)(b*Sz + k0 + r)*Dm + h*DKh + c];
        Ks[c+0][r] = bb.x; Ks[c+1][r] = bb.y; Ks[c+2][r] = bb.z; Ks[c+3][r] = bb.w;
    }
    __syncthreads();
    int ty = tid >> 4, tx = tid & 15;
    float acc[4][4] = {};
#pragma unroll
    for (int d = 0; d < 64; d++) {
        float4 av = *(float4*)&Qs[d][ty*4];
        float4 bv = *(float4*)&Ks[d][tx*4];
        acc[0][0] += av.x*bv.x; acc[0][1] += av.x*bv.y; acc[0][2] += av.x*bv.z; acc[0][3] += av.x*bv.w;
        acc[1][0] += av.y*bv.x; acc[1][1] += av.y*bv.y; acc[1][2] += av.y*bv.z; acc[1][3] += av.y*bv.w;
        acc[2][0] += av.z*bv.x; acc[2][1] += av.z*bv.y; acc[2][2] += av.z*bv.z; acc[2][3] += av.z*bv.w;
        acc[3][0] += av.w*bv.x; acc[3][1] += av.w*bv.y; acc[3][2] += av.w*bv.z; acc[3][3] += av.w*bv.w;
    }
#pragma unroll
    for (int i = 0; i < 4; i++)
#pragma unroll
        for (int j = 0; j < 4; j++) {
            float v = acc[i][j] * 0.125f;
            if (v == 0.f) v = NEGV;   // faithful: mask where score == 0
            sc[((size_t)bh*Sz + q0 + ty*4 + i)*Sz + k0 + tx*4 + j] = v;
        }
}

// ---------------- row softmax over 512 ----------------
__global__ void softmax512(float* __restrict__ s) {
    size_t row = blockIdx.x;
    float* p = s + row * Sz;
    int tid = threadIdx.x;                 // 128
    float4 v = *(float4*)&p[tid*4];
    float mx = fmaxf(fmaxf(v.x, v.y), fmaxf(v.z, v.w));
#pragma unroll
    for (int o = 16; o; o >>= 1) mx = fmaxf(mx, __shfl_xor_sync(0xffffffffu, mx, o));
    __shared__ float sm[4];
    if ((tid & 31) == 0) sm[tid >> 5] = mx;
    __syncthreads();
    mx = fmaxf(fmaxf(sm[0], sm[1]), fmaxf(sm[2], sm[3]));
    v.x = expf(v.x - mx); v.y = expf(v.y - mx);
    v.z = expf(v.z - mx); v.w = expf(v.w - mx);
    float sum = v.x + v.y + v.z + v.w;
#pragma unroll
    for (int o = 16; o; o >>= 1) sum += __shfl_xor_sync(0xffffffffu, sum, o);
    __shared__ float ss[4];
    if ((tid & 31) == 0) ss[tid >> 5] = sum;
    __syncthreads();
    sum = ss[0] + ss[1] + ss[2] + ss[3];
    float inv = 1.f / sum;
    v.x *= inv; v.y *= inv; v.z *= inv; v.w *= inv;
    *(float4*)&p[tid*4] = v;
}

// ---------------- O = P @ V ----------------
// grid (qtile=8, bh=64), block 256
__global__ void attn_pv(const float* __restrict__ P, const float* __restrict__ v,
                        float* __restrict__ o) {
    __shared__ float Ps[64][68];  // [k][q]
    __shared__ float Vs[64][64];  // [k][d]
    int bh = blockIdx.y, b = bh >> 3, h = bh & 7;
    int q0 = blockIdx.x * 64;
    int tid = threadIdx.x, ty = tid >> 4, tx = tid & 15;
    float acc[4][4] = {};
    for (int k0 = 0; k0 < Sz; k0 += 64) {
#pragma unroll
        for (int it = 0; it < 4; it++) {
            int idx = tid + it*256;
            int r = idx >> 4;
            int c = (idx & 15) * 4;
            float4 a = *(const float4*)&P[((size_t)bh*Sz + q0 + r)*Sz + k0 + c];
            Ps[c+0][r] = a.x; Ps[c+1][r] = a.y; Ps[c+2][r] = a.z; Ps[c+3][r] = a.w;
            float4 bb = *(const float4*)&v[(size_t)(b*Sz + k0 + r)*Dm + h*DKh + c];
            *(float4*)&Vs[r][c] = bb;
        }
        __syncthreads();
#pragma unroll
        for (int k = 0; k < 64; k++) {
            float4 av = *(float4*)&Ps[k][ty*4];
            float4 bv = *(float4*)&Vs[k][tx*4];
            acc[0][0] += av.x*bv.x; acc[0][1] += av.x*bv.y; acc[0][2] += av.x*bv.z; acc[0][3] += av.x*bv.w;
            acc[1][0] += av.y*bv.x; acc[1][1] += av.y*bv.y; acc[1][2] += av.y*bv.z; acc[1][3] += av.y*bv.w;
            acc[2][0] += av.z*bv.x; acc[2][1] += av.z*bv.y; acc[2][2] += av.z*bv.z; acc[2][3] += av.z*bv.w;
            acc[3][0] += av.w*bv.x; acc[3][1] += av.w*bv.y; acc[3][2] += av.w*bv.z; acc[3][3] += av.w*bv.w;
        }
        __syncthreads();
    }
#pragma unroll
    for (int i = 0; i < 4; i++)
#pragma unroll
        for (int j = 0; j < 4; j++)
            o[(size_t)(b*Sz + q0 + ty*4 + i)*Dm + h*DKh + tx*4 + j] = acc[i][j];
}

// ---------------- out = LayerNorm(a + res) * g + beta ----------------
// one block (128 thr) per row of 512
__global__ void add_ln(const float* __restrict__ a, const float* __restrict__ res,
                       const float* __restrict__ g, const float* __restrict__ beta,
                       float* __restrict__ out) {
    size_t row = blockIdx.x;
    int tid = threadIdx.x;
    int c = tid * 4;
    float4 av = *(const float4*)&a[row*Dm + c];
    float4 rv = *(const float4*)&res[row*Dm + c];
    float4 x;
    x.x = av.x + rv.x; x.y = av.y + rv.y; x.z = av.z + rv.z; x.w = av.w + rv.w;
    float s  = x.x + x.y + x.z + x.w;
    float s2 = x.x*x.x + x.y*x.y + x.z*x.z + x.w*x.w;
#pragma unroll
    for (int o = 16; o; o >>= 1) {
        s  += __shfl_xor_sync(0xffffffffu, s,  o);
        s2 += __shfl_xor_sync(0xffffffffu, s2, o);
    }
    __shared__ float sm[4], sq[4];
    if ((tid & 31) == 0) { sm[tid>>5] = s; sq[tid>>5] = s2; }
    __syncthreads();
    s  = sm[0] + sm[1] + sm[2] + sm[3];
    s2 = sq[0] + sq[1] + sq[2] + sq[3];
    float mean = s * (1.f/Dm);
    float var  = s2 * (1.f/Dm) - mean*mean;
    float inv  = rsqrtf(var + 1e-5f);
    float4 gv = *(const float4*)&g[c];
    float4 bv = *(const float4*)&beta[c];
    float4 y;
    y.x = (x.x - mean)*inv*gv.x + bv.x;
    y.y = (x.y - mean)*inv*gv.y + bv.y;
    y.z = (x.z - mean)*inv*gv.z + bv.z;
    y.w = (x.w - mean)*inv*gv.w + bv.w;
    *(float4*)&out[row*Dm + c] = y;
}

// ---------------- decoder cross-attention (Sq=1) ----------------
// grid (H, B), block 256
__global__ void cross_attn(const float* __restrict__ q, const float* __restrict__ k,
                           const float* __restrict__ v, float* __restrict__ o) {
    int h = blockIdx.x, b = blockIdx.y;
    __shared__ float qv[64];
    __shared__ float p[512];
    __shared__ float red[8];
    int tid = threadIdx.x;
    if (tid < 64) qv[tid] = q[b*Dm + h*DKh + tid];
    __syncthreads();
    float sc[2];
    float lmax = -INFINITY;
#pragma unroll
    for (int it = 0; it < 2; it++) {
        int j = tid + it*256;
        const float* kp = &k[(size_t)(b*Sz + j)*Dm + h*DKh];
        float s = 0.f;
#pragma unroll
        for (int c = 0; c < 64; c++) s += qv[c] * kp[c];
        s *= 0.125f;
        if (s == 0.f) s = NEGV;
        sc[it] = s;
        lmax = fmaxf(lmax, s);
    }
#pragma unroll
    for (int off = 16; off; off >>= 1) lmax = fmaxf(lmax, __shfl_xor_sync(0xffffffffu, lmax, off));
    if ((tid & 31) == 0) red[tid >> 5] = lmax;
    __syncthreads();
    float mx = red[0];
#pragma unroll
    for (int w = 1; w < 8; w++) mx = fmaxf(mx, red[w]);
    __syncthreads();
    float lsum = 0.f;
#pragma unroll
    for (int it = 0; it < 2; it++) {
        float e = expf(sc[it] - mx);
        p[tid + it*256] = e;
        lsum += e;
    }
#pragma unroll
    for (int off = 16; off; off >>= 1) lsum += __shfl_xor_sync(0xffffffffu, lsum, off);
    if ((tid & 31) == 0) red[tid >> 5] = lsum;
    __syncthreads();
    float sum = red[0] + red[1] + red[2] + red[3] + red[4] + red[5] + red[6] + red[7];
    float inv = 1.f / sum;
    int warp = tid >> 5, lane = tid & 31;
#pragma unroll
    for (int dd = 0; dd < 8; dd++) {
        int d = warp*8 + dd;
        float acc = 0.f;
        for (int j = lane; j < Sz; j += 32)
            acc += p[j] * v[(size_t)(b*Sz + j)*Dm + h*DKh + d];
#pragma unroll
        for (int off = 16; off; off >>= 1) acc += __shfl_xor_sync(0xffffffffu, acc, off);
        if (lane == 0) o[b*Dm + h*DKh + d] = acc * inv;
    }
}

// ---------------- tiny-M (M=8) GEMM for decoder: C[8,N]=A[8,K]@W+bias ------
__global__ void gemm8(const float* __restrict__ A, const float* __restrict__ W,
                      const float* __restrict__ bias, float* __restrict__ C,
                      int K, int N, int relu) {
    int col = blockIdx.x*blockDim.x + threadIdx.x;
    if (col >= N) return;
    float acc[8] = {};
    for (int k = 0; k < K; k++) {
        float wv = W[(size_t)k*N + col];
#pragma unroll
        for (int r = 0; r < 8; r++) acc[r] += A[r*K + k] * wv;
    }
    float bv = bias[col];
#pragma unroll
    for (int r = 0; r < 8; r++) {
        float val = acc[r] + bv;
        if (relu) val = fmaxf(val, 0.f);
        C[r*N + col] = val;
    }
}

// ---------------- host orchestration ----------------
extern "C" void kernel_launch(void* const* d_in, const int* in_sizes, int n_in,
                              void* d_out, int out_size) {
    const int*   x        = (const int*)d_in[0];
    const int*   tgt      = (const int*)d_in[1];
    const float* in_emb   = (const float*)d_in[2];
    const float* out_emb  = (const float*)d_in[3];
    const float* enc_qkv_w = (const float*)d_in[4];
    const float* enc_qkv_b = (const float*)d_in[5];
    const float* enc_ln1_g = (const float*)d_in[6];
    const float* enc_ln1_b = (const float*)d_in[7];
    const float* enc_ffn1_w = (const float*)d_in[8];
    const float* enc_ffn1_b = (const float*)d_in[9];
    const float* enc_ffn2_w = (const float*)d_in[10];
    const float* enc_ffn2_b = (const float*)d_in[11];
    const float* enc_ln2_g = (const float*)d_in[12];
    const float* enc_ln2_b = (const float*)d_in[13];
    const float* dec_qkv1_w = (const float*)d_in[14];
    const float* dec_qkv1_b = (const float*)d_in[15];
    const float* dec_ln1_g = (const float*)d_in[16];
    const float* dec_ln1_b = (const float*)d_in[17];
    const float* dec_qkv2_w = (const float*)d_in[18];
    const float* dec_qkv2_b = (const float*)d_in[19];
    const float* dec_ln2_g = (const float*)d_in[20];
    const float* dec_ln2_b = (const float*)d_in[21];
    const float* dec_ffn1_w = (const float*)d_in[22];
    const float* dec_ffn1_b = (const float*)d_in[23];
    const float* dec_ffn2_w = (const float*)d_in[24];
    const float* dec_ffn2_b = (const float*)d_in[25];
    const float* dec_ln3_g = (const float*)d_in[26];
    const float* dec_ln3_b = (const float*)d_in[27];
    const float* out_w = (const float*)d_in[28];
    const float* out_b = (const float*)d_in[29];

    float *e, *q, *k, *v, *sc, *attn, *hbuf, *tbuf, *dbuf, *dq, *dt, *dh;
    cudaGetSymbolAddress((void**)&e,    g_e);
    cudaGetSymbolAddress((void**)&q,    g_q);
    cudaGetSymbolAddress((void**)&k,    g_k);
    cudaGetSymbolAddress((void**)&v,    g_v);
    cudaGetSymbolAddress((void**)&sc,   g_sc);
    cudaGetSymbolAddress((void**)&attn, g_attn);
    cudaGetSymbolAddress((void**)&hbuf, g_h);
    cudaGetSymbolAddress((void**)&tbuf, g_t);
    cudaGetSymbolAddress((void**)&dbuf, g_d);
    cudaGetSymbolAddress((void**)&dq,   g_dq);
    cudaGetSymbolAddress((void**)&dt,   g_dt);
    cudaGetSymbolAddress((void**)&dh,   g_dh);

    const int M = Bz*Sz;            // 4096
    dim3 gD(Dm/64, M/64);           // N=512
    dim3 gF1(DFFz/64, M/64);        // N=2048

    // ---------------- encoder ----------------
    embed_enc<<<(Bz*Sz*Dm + 255)/256, 256>>>(x, in_emb, e);
    for (int i = 0; i < Lz; i++) {
        sgemm<0><<<gD, 256>>>(e, enc_qkv_w + (size_t)(i*3+0)*Dm*Dm, enc_qkv_b + (i*3+0)*Dm, q, M, Dm, Dm);
        sgemm<0><<<gD, 256>>>(e, enc_qkv_w + (size_t)(i*3+1)*Dm*Dm, enc_qkv_b + (i*3+1)*Dm, k, M, Dm, Dm);
        sgemm<0><<<gD, 256>>>(e, enc_qkv_w + (size_t)(i*3+2)*Dm*Dm, enc_qkv_b + (i*3+2)*Dm, v, M, Dm, Dm);
        attn_scores<<<dim3(8, 8, Bz*Hn), 256>>>(q, k, sc);
        softmax512<<<Bz*Hn*Sz, 128>>>(sc);
        attn_pv<<<dim3(8, Bz*Hn), 256>>>(sc, v, attn);
        add_ln<<<M, 128>>>(attn, e, enc_ln1_g + i*Dm, enc_ln1_b + i*Dm, e);
        sgemm<1><<<gF1, 256>>>(e, enc_ffn1_w + (size_t)i*Dm*DFFz, enc_ffn1_b + i*DFFz, hbuf, M, DFFz, Dm);
        sgemm<0><<<gD, 256>>>(hbuf, enc_ffn2_w + (size_t)i*DFFz*Dm, enc_ffn2_b + i*Dm, tbuf, M, Dm, DFFz);
        add_ln<<<M, 128>>>(tbuf, e, enc_ln2_g + i*Dm, enc_ln2_b + i*Dm, e);
    }

    // ---------------- decoder (seq len 1; self-attn output == V projection) --
    embed_dec<<<(Bz*Dm + 255)/256, 256>>>(tgt, out_emb, dbuf);
    for (int i = 0; i < Lz; i++) {
        // self-attn: softmax over 1 element == 1 -> out = v
        gemm8<<<(Dm+127)/128, 128>>>(dbuf, dec_qkv1_w + (size_t)(i*3+2)*Dm*Dm, dec_qkv1_b + (i*3+2)*Dm, dt, Dm, Dm, 0);
        add_ln<<<Bz, 128>>>(dt, dbuf, dec_ln1_g + i*Dm, dec_ln1_b + i*Dm, dbuf);
        // cross-attn
        gemm8<<<(Dm+127)/128, 128>>>(dbuf, dec_qkv2_w + (size_t)(i*3+0)*Dm*Dm, dec_qkv2_b + (i*3+0)*Dm, dq, Dm, Dm, 0);
        sgemm<0><<<gD, 256>>>(e, dec_qkv2_w + (size_t)(i*3+1)*Dm*Dm, dec_qkv2_b + (i*3+1)*Dm, q, M, Dm, Dm); // K
        sgemm<0><<<gD, 256>>>(e, dec_qkv2_w + (size_t)(i*3+2)*Dm*Dm, dec_qkv2_b + (i*3+2)*Dm, k, M, Dm, Dm); // V
        cross_attn<<<dim3(Hn, Bz), 256>>>(dq, q, k, dt);
        add_ln<<<Bz, 128>>>(dt, dbuf, dec_ln2_g + i*Dm, dec_ln2_b + i*Dm, dbuf);
        // FFN
        gemm8<<<(DFFz+127)/128, 128>>>(dbuf, dec_ffn1_w + (size_t)i*Dm*DFFz, dec_ffn1_b + i*DFFz, dh, Dm, DFFz, 1);
        gemm8<<<(Dm+127)/128, 128>>>(dh, dec_ffn2_w + (size_t)i*DFFz*Dm, dec_ffn2_b + i*Dm, dt, DFFz, Dm, 0);
        add_ln<<<Bz, 128>>>(dt, dbuf, dec_ln3_g + i*Dm, dec_ln3_b + i*Dm, dbuf);
    }

    // output projection -> d_out [8,1,1000]
    gemm8<<<(OUTz+127)/128, 128>>>(dbuf, out_w, out_b, (float*)d_out, Dm, OUTz, 0);
    (void)in_sizes; (void)n_in; (void)out_size;
}

// round 3
// speedup vs baseline: 1.3278x; 1.3278x over previous
#include <cuda_runtime.h>
#include <cuda_bf16.h>
#include <math.h>
#include <stdint.h>

#define Bz   8
#define Sz   512
#define Dm   512
#define Hn   8
#define DKh  64
#define Lz   6
#define DFFz 2048
#define OUTz 1000
#define NEGV (-1e9f)

// ---------------- scratch (device globals: allowed) ----------------
__device__ float g_e[Bz*Sz*Dm];
__device__ float g_qkv[3*Bz*Sz*Dm];
__device__ float g_sc[(size_t)Bz*Hn*Sz*Sz];
__device__ float g_attn[Bz*Sz*Dm];
__device__ float g_h[Bz*Sz*DFFz];
__device__ float g_t[Bz*Sz*Dm];
__device__ float g_d[Bz*Dm];
__device__ float g_dq[Bz*Dm];
__device__ float g_dt[Bz*Dm];
__device__ float g_dh[Bz*DFFz];

// ---------------- embedding + positional encoding (fp32 math) --------------
__global__ void embed_enc(const int* __restrict__ x, const float* __restrict__ emb,
                          float* __restrict__ e) {
    int idx = blockIdx.x*blockDim.x + threadIdx.x;
    if (idx >= Bz*Sz*Dm) return;
    int d  = idx % Dm;
    int bs = idx / Dm;
    int s  = bs % Sz;
    int tok = x[bs];
    // 2^(-(2i) * log2(10000)/Dm)
    float div = exp2f(-(float)(d & ~1) * (13.287712379549449f / (float)Dm));
    float arg = (float)s * div;
    float pe = (d & 1) ? cosf(arg) : sinf(arg);
    e[idx] = emb[tok*Dm + d] * 22.627416997969522f + pe;
}

__global__ void embed_dec(const int* __restrict__ tgt, const float* __restrict__ emb,
                          float* __restrict__ o) {
    int idx = blockIdx.x*blockDim.x + threadIdx.x;
    if (idx >= Bz*Dm) return;
    int d = idx % Dm;
    int b = idx / Dm;
    float pe = (d & 1) ? 1.f : 0.f;   // PE[0]: sin(0)=0, cos(0)=1
    o[idx] = emb[tgt[b]*Dm + d] * 22.627416997969522f + pe;
}

// ======================= tensor-core GEMM (bf16x3 split) ====================
// C[M,N] = A[M,K] @ B[K,N] (+bias, +relu / scores epilogue)
// BM=128, BN=64, BK=32, 256 threads = 8 warps (4 along M x 2 along N),
// each warp 32x32 via mma.sync.m16n8k16.bf16, fp32 accumulate.
// bf16x3: hi*hi + hi*lo + lo*hi  ->  ~fp32 accuracy.
// Batched via blockIdx.z with decomposed strides: off = (z/zdiv)*s1 + (z%zdiv)*s2.
// EPI: 0 = +bias, 1 = +bias+relu, 2 = *0.125 & (==0 -> NEGV), 3 = none.
// TB:  0 = B row-major [K,N] (elem = B[k*ldb+n]); 1 = B transposed (elem = B[n*ldb+k]).

#define BM 128
#define BN 64
#define BKt 32
#define APAD 34

__device__ __forceinline__ void mma_bf16(float c[4], const uint32_t a[4], const uint32_t b[2]) {
    asm volatile(
        "mma.sync.aligned.m16n8k16.row.col.f32.bf16.bf16.f32 "
        "{%0,%1,%2,%3}, {%4,%5,%6,%7}, {%8,%9}, {%0,%1,%2,%3};\n"
        : "+f"(c[0]), "+f"(c[1]), "+f"(c[2]), "+f"(c[3])
        : "r"(a[0]), "r"(a[1]), "r"(a[2]), "r"(a[3]), "r"(b[0]), "r"(b[1]));
}

template<int EPI, int TB>
__global__ __launch_bounds__(256)
void gemm_tc(const float* __restrict__ A, const float* __restrict__ Bm,
             const float* __restrict__ bias, float* __restrict__ C,
             int M, int N, int K, int lda, int ldb, int ldc,
             int zdiv, long long sA1, long long sA2, long long sB1, long long sB2,
             long long sC1, long long sC2, long long sBias) {
    __shared__ __nv_bfloat16 Ah[BM][APAD], Al[BM][APAD];
    __shared__ __nv_bfloat16 Bh[BN][APAD], Bl[BN][APAD];

    int z = blockIdx.z;
    int z1 = z / zdiv, z2 = z % zdiv;
    const float* Ab = A  + z1*sA1 + z2*sA2;
    const float* Bb = Bm + z1*sB1 + z2*sB2;
    float*       Cb = C  + z1*sC1 + z2*sC2;

    int m0 = blockIdx.y * BM, n0 = blockIdx.x * BN;
    int tid = threadIdx.x;
    int wid = tid >> 5, lane = tid & 31;
    int warp_m = wid & 3, warp_n = wid >> 2;   // 4 x 2 warp grid
    int gid = lane >> 2, tig = lane & 3;

    float acc[2][4][4] = {};

    for (int k0 = 0; k0 < K; k0 += BKt) {
        // ---- load & split A tile: 128x32 ----
        {
            int r  = tid >> 3;           // 0..31
            int c4 = (tid & 7) * 4;
#pragma unroll
            for (int p = 0; p < 4; p++) {
                int row = p*32 + r;
                float4 v = *(const float4*)&Ab[(size_t)(m0+row)*lda + k0 + c4];
                float vv[4] = {v.x, v.y, v.z, v.w};
#pragma unroll
                for (int j = 0; j < 4; j++) {
                    __nv_bfloat16 h = __float2bfloat16(vv[j]);
                    Ah[row][c4+j] = h;
                    Al[row][c4+j] = __float2bfloat16(vv[j] - __bfloat162float(h));
                }
            }
        }
        // ---- load & split B tile into [n][k] layout ----
        if (TB) {
            int n  = tid >> 3;           // 0..31
            int c4 = (tid & 7) * 4;
#pragma unroll
            for (int p = 0; p < 2; p++) {
                int nn = p*32 + n;
                float4 v = *(const float4*)&Bb[(size_t)(n0+nn)*ldb + k0 + c4];
                float vv[4] = {v.x, v.y, v.z, v.w};
#pragma unroll
                for (int j = 0; j < 4; j++) {
                    __nv_bfloat16 h = __float2bfloat16(vv[j]);
                    Bh[nn][c4+j] = h;
                    Bl[nn][c4+j] = __float2bfloat16(vv[j] - __bfloat162float(h));
                }
            }
        } else {
            int kk = tid >> 4;           // 0..15
            int n4 = (tid & 15) * 4;
#pragma unroll
            for (int p = 0; p < 2; p++) {
                int kr = p*16 + kk;
                float4 v = *(const float4*)&Bb[(size_t)(k0+kr)*ldb + n0 + n4];
                float vv[4] = {v.x, v.y, v.z, v.w};
#pragma unroll
                for (int j = 0; j < 4; j++) {
                    __nv_bfloat16 h = __float2bfloat16(vv[j]);
                    Bh[n4+j][kr] = h;
                    Bl[n4+j][kr] = __float2bfloat16(vv[j] - __bfloat162float(h));
                }
            }
        }
        __syncthreads();

        // ---- compute: 2 k16 slabs ----
#pragma unroll
        for (int kk = 0; kk < 2; kk++) {
            int kc = kk*16 + tig*2;
            uint32_t ah[2][4], al[2][4], bh[4][2], bl[4][2];
#pragma unroll
            for (int mi = 0; mi < 2; mi++) {
                int row = warp_m*32 + mi*16 + gid;
                ah[mi][0] = *(const uint32_t*)&Ah[row  ][kc  ];
                ah[mi][1] = *(const uint32_t*)&Ah[row+8][kc  ];
                ah[mi][2] = *(const uint32_t*)&Ah[row  ][kc+8];
                ah[mi][3] = *(const uint32_t*)&Ah[row+8][kc+8];
                al[mi][0] = *(const uint32_t*)&Al[row  ][kc  ];
                al[mi][1] = *(const uint32_t*)&Al[row+8][kc  ];
                al[mi][2] = *(const uint32_t*)&Al[row  ][kc+8];
                al[mi][3] = *(const uint32_t*)&Al[row+8][kc+8];
            }
#pragma unroll
            for (int ni = 0; ni < 4; ni++) {
                int n = warp_n*32 + ni*8 + gid;
                bh[ni][0] = *(const uint32_t*)&Bh[n][kc  ];
                bh[ni][1] = *(const uint32_t*)&Bh[n][kc+8];
                bl[ni][0] = *(const uint32_t*)&Bl[n][kc  ];
                bl[ni][1] = *(const uint32_t*)&Bl[n][kc+8];
            }
#pragma unroll
            for (int mi = 0; mi < 2; mi++)
#pragma unroll
                for (int ni = 0; ni < 4; ni++) {
                    mma_bf16(acc[mi][ni], ah[mi], bh[ni]);
                    mma_bf16(acc[mi][ni], ah[mi], bl[ni]);
                    mma_bf16(acc[mi][ni], al[mi], bh[ni]);
                }
        }
        __syncthreads();
    }

    // ---- epilogue ----
    const float* biasb = (EPI <= 1) ? bias + (long long)z * sBias : nullptr;
#pragma unroll
    for (int mi = 0; mi < 2; mi++)
#pragma unroll
        for (int ni = 0; ni < 4; ni++) {
            int row = m0 + warp_m*32 + mi*16 + gid;
            int col = n0 + warp_n*32 + ni*8 + tig*2;
#pragma unroll
            for (int e2 = 0; e2 < 4; e2++) {
                int r  = row + (e2 >> 1)*8;
                int cc = col + (e2 & 1);
                float v = acc[mi][ni][e2];
                if (EPI == 0 || EPI == 1) v += biasb[cc];
                if (EPI == 1) v = fmaxf(v, 0.f);
                if (EPI == 2) { v *= 0.125f; if (v == 0.f) v = NEGV; }
                Cb[(size_t)r*ldc + cc] = v;
            }
        }
}

// ---------------- row softmax over 512 ----------------
__global__ void softmax512(float* __restrict__ s) {
    size_t row = blockIdx.x;
    float* p = s + row * Sz;
    int tid = threadIdx.x;                 // 128
    float4 v = *(float4*)&p[tid*4];
    float mx = fmaxf(fmaxf(v.x, v.y), fmaxf(v.z, v.w));
#pragma unroll
    for (int o = 16; o; o >>= 1) mx = fmaxf(mx, __shfl_xor_sync(0xffffffffu, mx, o));
    __shared__ float sm[4];
    if ((tid & 31) == 0) sm[tid >> 5] = mx;
    __syncthreads();
    mx = fmaxf(fmaxf(sm[0], sm[1]), fmaxf(sm[2], sm[3]));
    v.x = expf(v.x - mx); v.y = expf(v.y - mx);
    v.z = expf(v.z - mx); v.w = expf(v.w - mx);
    float sum = v.x + v.y + v.z + v.w;
#pragma unroll
    for (int o = 16; o; o >>= 1) sum += __shfl_xor_sync(0xffffffffu, sum, o);
    __shared__ float ss[4];
    if ((tid & 31) == 0) ss[tid >> 5] = sum;
    __syncthreads();
    sum = ss[0] + ss[1] + ss[2] + ss[3];
    float inv = 1.f / sum;
    v.x *= inv; v.y *= inv; v.z *= inv; v.w *= inv;
    *(float4*)&p[tid*4] = v;
}

// ---------------- out = LayerNorm(a + res) * g + beta ----------------
__global__ void add_ln(const float* __restrict__ a, const float* __restrict__ res,
                       const float* __restrict__ g, const float* __restrict__ beta,
                       float* __restrict__ out) {
    size_t row = blockIdx.x;
    int tid = threadIdx.x;
    int c = tid * 4;
    float4 av = *(const float4*)&a[row*Dm + c];
    float4 rv = *(const float4*)&res[row*Dm + c];
    float4 x;
    x.x = av.x + rv.x; x.y = av.y + rv.y; x.z = av.z + rv.z; x.w = av.w + rv.w;
    float s  = x.x + x.y + x.z + x.w;
    float s2 = x.x*x.x + x.y*x.y + x.z*x.z + x.w*x.w;
#pragma unroll
    for (int o = 16; o; o >>= 1) {
        s  += __shfl_xor_sync(0xffffffffu, s,  o);
        s2 += __shfl_xor_sync(0xffffffffu, s2, o);
    }
    __shared__ float sm[4], sq[4];
    if ((tid & 31) == 0) { sm[tid>>5] = s; sq[tid>>5] = s2; }
    __syncthreads();
    s  = sm[0] + sm[1] + sm[2] + sm[3];
    s2 = sq[0] + sq[1] + sq[2] + sq[3];
    float mean = s * (1.f/Dm);
    float var  = s2 * (1.f/Dm) - mean*mean;
    float inv  = rsqrtf(var + 1e-5f);
    float4 gv = *(const float4*)&g[c];
    float4 bv = *(const float4*)&beta[c];
    float4 y;
    y.x = (x.x - mean)*inv*gv.x + bv.x;
    y.y = (x.y - mean)*inv*gv.y + bv.y;
    y.z = (x.z - mean)*inv*gv.z + bv.z;
    y.w = (x.w - mean)*inv*gv.w + bv.w;
    *(float4*)&out[row*Dm + c] = y;
}

// ---------------- decoder cross-attention (Sq=1) ----------------
__global__ void cross_attn(const float* __restrict__ q, const float* __restrict__ k,
                           const float* __restrict__ v, float* __restrict__ o) {
    int h = blockIdx.x, b = blockIdx.y;
    __shared__ float qv[64];
    __shared__ float p[512];
    __shared__ float red[8];
    int tid = threadIdx.x;
    if (tid < 64) qv[tid] = q[b*Dm + h*DKh + tid];
    __syncthreads();
    float sc[2];
    float lmax = -INFINITY;
#pragma unroll
    for (int it = 0; it < 2; it++) {
        int j = tid + it*256;
        const float* kp = &k[(size_t)(b*Sz + j)*Dm + h*DKh];
        float s = 0.f;
#pragma unroll
        for (int c = 0; c < 64; c++) s += qv[c] * kp[c];
        s *= 0.125f;
        if (s == 0.f) s = NEGV;
        sc[it] = s;
        lmax = fmaxf(lmax, s);
    }
#pragma unroll
    for (int off = 16; off; off >>= 1) lmax = fmaxf(lmax, __shfl_xor_sync(0xffffffffu, lmax, off));
    if ((tid & 31) == 0) red[tid >> 5] = lmax;
    __syncthreads();
    float mx = red[0];
#pragma unroll
    for (int w = 1; w < 8; w++) mx = fmaxf(mx, red[w]);
    __syncthreads();
    float lsum = 0.f;
#pragma unroll
    for (int it = 0; it < 2; it++) {
        float e = expf(sc[it] - mx);
        p[tid + it*256] = e;
        lsum += e;
    }
#pragma unroll
    for (int off = 16; off; off >>= 1) lsum += __shfl_xor_sync(0xffffffffu, lsum, off);
    if ((tid & 31) == 0) red[tid >> 5] = lsum;
    __syncthreads();
    float sum = red[0] + red[1] + red[2] + red[3] + red[4] + red[5] + red[6] + red[7];
    float inv = 1.f / sum;
    int warp = tid >> 5, lane = tid & 31;
#pragma unroll
    for (int dd = 0; dd < 8; dd++) {
        int d = warp*8 + dd;
        float acc = 0.f;
        for (int j = lane; j < Sz; j += 32)
            acc += p[j] * v[(size_t)(b*Sz + j)*Dm + h*DKh + d];
#pragma unroll
        for (int off = 16; off; off >>= 1) acc += __shfl_xor_sync(0xffffffffu, acc, off);
        if (lane == 0) o[b*Dm + h*DKh + d] = acc * inv;
    }
}

// ---------------- tiny-M (M=8) GEMM for decoder ----------------
__global__ void gemm8(const float* __restrict__ A, const float* __restrict__ W,
                      const float* __restrict__ bias, float* __restrict__ C,
                      int K, int N, int relu) {
    int col = blockIdx.x*blockDim.x + threadIdx.x;
    if (col >= N) return;
    float acc[8] = {};
    for (int k = 0; k < K; k++) {
        float wv = W[(size_t)k*N + col];
#pragma unroll
        for (int r = 0; r < 8; r++) acc[r] += A[r*K + k] * wv;
    }
    float bv = bias[col];
#pragma unroll
    for (int r = 0; r < 8; r++) {
        float val = acc[r] + bv;
        if (relu) val = fmaxf(val, 0.f);
        C[r*N + col] = val;
    }
}

// ---------------- host orchestration ----------------
extern "C" void kernel_launch(void* const* d_in, const int* in_sizes, int n_in,
                              void* d_out, int out_size) {
    const int*   x        = (const int*)d_in[0];
    const int*   tgt      = (const int*)d_in[1];
    const float* in_emb   = (const float*)d_in[2];
    const float* out_emb  = (const float*)d_in[3];
    const float* enc_qkv_w = (const float*)d_in[4];
    const float* enc_qkv_b = (const float*)d_in[5];
    const float* enc_ln1_g = (const float*)d_in[6];
    const float* enc_ln1_b = (const float*)d_in[7];
    const float* enc_ffn1_w = (const float*)d_in[8];
    const float* enc_ffn1_b = (const float*)d_in[9];
    const float* enc_ffn2_w = (const float*)d_in[10];
    const float* enc_ffn2_b = (const float*)d_in[11];
    const float* enc_ln2_g = (const float*)d_in[12];
    const float* enc_ln2_b = (const float*)d_in[13];
    const float* dec_qkv1_w = (const float*)d_in[14];
    const float* dec_qkv1_b = (const float*)d_in[15];
    const float* dec_ln1_g = (const float*)d_in[16];
    const float* dec_ln1_b = (const float*)d_in[17];
    const float* dec_qkv2_w = (const float*)d_in[18];
    const float* dec_qkv2_b = (const float*)d_in[19];
    const float* dec_ln2_g = (const float*)d_in[20];
    const float* dec_ln2_b = (const float*)d_in[21];
    const float* dec_ffn1_w = (const float*)d_in[22];
    const float* dec_ffn1_b = (const float*)d_in[23];
    const float* dec_ffn2_w = (const float*)d_in[24];
    const float* dec_ffn2_b = (const float*)d_in[25];
    const float* dec_ln3_g = (const float*)d_in[26];
    const float* dec_ln3_b = (const float*)d_in[27];
    const float* out_w = (const float*)d_in[28];
    const float* out_b = (const float*)d_in[29];

    float *e, *qkv, *sc, *attn, *hbuf, *tbuf, *dbuf, *dq, *dt, *dh;
    cudaGetSymbolAddress((void**)&e,    g_e);
    cudaGetSymbolAddress((void**)&qkv,  g_qkv);
    cudaGetSymbolAddress((void**)&sc,   g_sc);
    cudaGetSymbolAddress((void**)&attn, g_attn);
    cudaGetSymbolAddress((void**)&hbuf, g_h);
    cudaGetSymbolAddress((void**)&tbuf, g_t);
    cudaGetSymbolAddress((void**)&dbuf, g_d);
    cudaGetSymbolAddress((void**)&dq,   g_dq);
    cudaGetSymbolAddress((void**)&dt,   g_dt);
    cudaGetSymbolAddress((void**)&dh,   g_dh);

    const int M = Bz*Sz;            // 4096
    const long long DD = (long long)Dm*Dm;
    const long long MD = (long long)M*Dm;
    const long long SS = (long long)Sz*Sz;
    const long long SDm = (long long)Sz*Dm;
    float* qb = qkv;                // q / cross-K
    float* kb = qkv + MD;           // k / cross-V
    float* vb = qkv + 2*MD;         // v

    // ---------------- encoder ----------------
    embed_enc<<<(Bz*Sz*Dm + 255)/256, 256>>>(x, in_emb, e);
    for (int i = 0; i < Lz; i++) {
        // fused QKV: batch z=3 over weight matrices
        gemm_tc<0,0><<<dim3(Dm/BN, M/BM, 3), 256>>>(
            e, enc_qkv_w + (size_t)i*3*DD, enc_qkv_b + (size_t)i*3*Dm, qkv,
            M, Dm, Dm, Dm, Dm, Dm,
            1, 0, 0, DD, 0, MD, 0, Dm);
        // scores: per (b,h), C = Q Kt / 8 with quirky mask
        gemm_tc<2,1><<<dim3(Sz/BN, Sz/BM, Bz*Hn), 256>>>(
            qb, kb, nullptr, sc,
            Sz, Sz, DKh, Dm, Dm, Sz,
            Hn, SDm, DKh, SDm, DKh, (long long)Hn*SS, SS, 0);
        softmax512<<<Bz*Hn*Sz, 128>>>(sc);
        // PV: per (b,h), C = P V
        gemm_tc<3,0><<<dim3(DKh/BN, Sz/BM, Bz*Hn), 256>>>(
            sc, vb, nullptr, attn,
            Sz, DKh, Sz, Sz, Dm, Dm,
            Hn, (long long)Hn*SS, SS, SDm, DKh, SDm, DKh, 0);
        add_ln<<<M, 128>>>(attn, e, enc_ln1_g + i*Dm, enc_ln1_b + i*Dm, e);
        gemm_tc<1,0><<<dim3(DFFz/BN, M/BM, 1), 256>>>(
            e, enc_ffn1_w + (size_t)i*Dm*DFFz, enc_ffn1_b + (size_t)i*DFFz, hbuf,
            M, DFFz, Dm, Dm, DFFz, DFFz,
            1, 0, 0, 0, 0, 0, 0, 0);
        gemm_tc<0,0><<<dim3(Dm/BN, M/BM, 1), 256>>>(
            hbuf, enc_ffn2_w + (size_t)i*DFFz*Dm, enc_ffn2_b + (size_t)i*Dm, tbuf,
            M, Dm, DFFz, DFFz, Dm, Dm,
            1, 0, 0, 0, 0, 0, 0, 0);
        add_ln<<<M, 128>>>(tbuf, e, enc_ln2_g + i*Dm, enc_ln2_b + i*Dm, e);
    }

    // ---------------- decoder (seq len 1; self-attn == V projection) --------
    embed_dec<<<(Bz*Dm + 255)/256, 256>>>(tgt, out_emb, dbuf);
    for (int i = 0; i < Lz; i++) {
        gemm8<<<(Dm+127)/128, 128>>>(dbuf, dec_qkv1_w + (size_t)(i*3+2)*DD, dec_qkv1_b + (i*3+2)*Dm, dt, Dm, Dm, 0);
        add_ln<<<Bz, 128>>>(dt, dbuf, dec_ln1_g + i*Dm, dec_ln1_b + i*Dm, dbuf);
        // cross-attn: q from decoder state; K,V projections of encoder output (batch z=2)
        gemm8<<<(Dm+127)/128, 128>>>(dbuf, dec_qkv2_w + (size_t)(i*3+0)*DD, dec_qkv2_b + (i*3+0)*Dm, dq, Dm, Dm, 0);
        gemm_tc<0,0><<<dim3(Dm/BN, M/BM, 2), 256>>>(
            e, dec_qkv2_w + (size_t)(i*3+1)*DD, dec_qkv2_b + (size_t)(i*3+1)*Dm, qkv,
            M, Dm, Dm, Dm, Dm, Dm,
            1, 0, 0, DD, 0, MD, 0, Dm);
        cross_attn<<<dim3(Hn, Bz), 256>>>(dq, qb /*K*/, kb /*V*/, dt);
        add_ln<<<Bz, 128>>>(dt, dbuf, dec_ln2_g + i*Dm, dec_ln2_b + i*Dm, dbuf);
        gemm8<<<(DFFz+127)/128, 128>>>(dbuf, dec_ffn1_w + (size_t)i*Dm*DFFz, dec_ffn1_b + i*DFFz, dh, Dm, DFFz, 1);
        gemm8<<<(Dm+127)/128, 128>>>(dh, dec_ffn2_w + (size_t)i*DFFz*Dm, dec_ffn2_b + i*Dm, dt, DFFz, Dm, 0);
        add_ln<<<Bz, 128>>>(dt, dbuf, dec_ln3_g + i*Dm, dec_ln3_b + i*Dm, dbuf);
    }

    // output projection -> d_out [8,1,1000]
    gemm8<<<(OUTz+127)/128, 128>>>(dbuf, out_w, out_b, (float*)d_out, Dm, OUTz, 0);
    (void)in_sizes; (void)n_in; (void)out_size;
}

// round 4
// speedup vs baseline: 1.4580x; 1.0981x over previous
#include <cuda_runtime.h>
#include <cuda_bf16.h>
#include <math.h>
#include <stdint.h>

#define Bz   8
#define Sz   512
#define Dm   512
#define Hn   8
#define DKh  64
#define Lz   6
#define DFFz 2048
#define OUTz 1000
#define NEGV (-1e9f)

// ---------------- scratch (device globals) ----------------
__device__ float g_e[Bz*Sz*Dm];
__device__ __nv_bfloat16 g_ehi[Bz*Sz*Dm], g_elo[Bz*Sz*Dm];
__device__ __nv_bfloat16 g_qkvh[3*Bz*Sz*Dm], g_qkvl[3*Bz*Sz*Dm];
__device__ float g_kvf[2*Bz*Sz*Dm];                       // decoder cross K/V (f32)
__device__ float g_sc[(size_t)Bz*Hn*Sz*Sz];
__device__ __nv_bfloat16 g_schi[(size_t)Bz*Hn*Sz*Sz], g_sclo[(size_t)Bz*Hn*Sz*Sz];
__device__ float g_attn[Bz*Sz*Dm];
__device__ __nv_bfloat16 g_hhi[Bz*Sz*DFFz], g_hlo[Bz*Sz*DFFz];
__device__ float g_t[Bz*Sz*Dm];
__device__ float g_d[Bz*Dm];
__device__ float g_dq[Bz*Dm];
__device__ float g_dt[Bz*Dm];
__device__ float g_dh[Bz*DFFz];
// weight split planes
__device__ __nv_bfloat16 g_wqkvh[Lz*3*Dm*Dm], g_wqkvl[Lz*3*Dm*Dm];
__device__ __nv_bfloat16 g_wf1h[Lz*Dm*DFFz],  g_wf1l[Lz*Dm*DFFz];
__device__ __nv_bfloat16 g_wf2h[Lz*DFFz*Dm],  g_wf2l[Lz*DFFz*Dm];
__device__ __nv_bfloat16 g_wd2h[Lz*3*Dm*Dm],  g_wd2l[Lz*3*Dm*Dm];

// ---------------- helpers ----------------
__device__ __forceinline__ void cpa(void* dst, const void* src) {
    uint32_t d = (uint32_t)__cvta_generic_to_shared(dst);
    asm volatile("cp.async.ca.shared.global [%0], [%1], 16;\n" :: "r"(d), "l"(src));
}
__device__ __forceinline__ void ldsm4(uint32_t& r0, uint32_t& r1, uint32_t& r2, uint32_t& r3,
                                      const void* p) {
    uint32_t a = (uint32_t)__cvta_generic_to_shared(p);
    asm volatile("ldmatrix.sync.aligned.m8n8.x4.shared.b16 {%0,%1,%2,%3}, [%4];\n"
                 : "=r"(r0), "=r"(r1), "=r"(r2), "=r"(r3) : "r"(a));
}
__device__ __forceinline__ void ldsm4t(uint32_t& r0, uint32_t& r1, uint32_t& r2, uint32_t& r3,
                                       const void* p) {
    uint32_t a = (uint32_t)__cvta_generic_to_shared(p);
    asm volatile("ldmatrix.sync.aligned.m8n8.x4.trans.shared.b16 {%0,%1,%2,%3}, [%4];\n"
                 : "=r"(r0), "=r"(r1), "=r"(r2), "=r"(r3) : "r"(a));
}
__device__ __forceinline__ void mma_bf16(float c[4], const uint32_t a[4], const uint32_t b[2]) {
    asm volatile(
        "mma.sync.aligned.m16n8k16.row.col.f32.bf16.bf16.f32 "
        "{%0,%1,%2,%3}, {%4,%5,%6,%7}, {%8,%9}, {%0,%1,%2,%3};\n"
        : "+f"(c[0]), "+f"(c[1]), "+f"(c[2]), "+f"(c[3])
        : "r"(a[0]), "r"(a[1]), "r"(a[2]), "r"(a[3]), "r"(b[0]), "r"(b[1]));
}

// ---------------- split f32 -> bf16 hi/lo ----------------
__global__ void splitk(const float* __restrict__ src, __nv_bfloat16* __restrict__ hi,
                       __nv_bfloat16* __restrict__ lo, int n) {
    int i = blockIdx.x*blockDim.x + threadIdx.x;
    if (i >= n) return;
    float v = src[i];
    __nv_bfloat16 h = __float2bfloat16(v);
    hi[i] = h;
    lo[i] = __float2bfloat16(v - __bfloat162float(h));
}

// ---------------- embedding + PE (writes f32 + split) ----------------
__global__ void embed_enc(const int* __restrict__ x, const float* __restrict__ emb,
                          float* __restrict__ e, __nv_bfloat16* __restrict__ ehi,
                          __nv_bfloat16* __restrict__ elo) {
    int idx = blockIdx.x*blockDim.x + threadIdx.x;
    if (idx >= Bz*Sz*Dm) return;
    int d  = idx % Dm;
    int bs = idx / Dm;
    int s  = bs % Sz;
    int tok = x[bs];
    float div = exp2f(-(float)(d & ~1) * (13.287712379549449f / (float)Dm));
    float arg = (float)s * div;
    float pe = (d & 1) ? cosf(arg) : sinf(arg);
    float v = emb[tok*Dm + d] * 22.627416997969522f + pe;
    e[idx] = v;
    __nv_bfloat16 h = __float2bfloat16(v);
    ehi[idx] = h;
    elo[idx] = __float2bfloat16(v - __bfloat162float(h));
}

__global__ void embed_dec(const int* __restrict__ tgt, const float* __restrict__ emb,
                          float* __restrict__ o) {
    int idx = blockIdx.x*blockDim.x + threadIdx.x;
    if (idx >= Bz*Dm) return;
    int d = idx % Dm;
    int b = idx / Dm;
    float pe = (d & 1) ? 1.f : 0.f;
    o[idx] = emb[tgt[b]*Dm + d] * 22.627416997969522f + pe;
}

// ======================= pipelined tensor-core GEMM (pre-split bf16x3) ======
// C[M,N] = A[M,K] @ B[K,N]; A,B given as bf16 hi/lo planes.
// BM=BN=64, BK=32, 128 threads = 4 warps (2x2), warp tile 32x32.
// TB: 0 = B row-major [K,N] (ldmatrix.trans); 1 = B is [N,K] (direct).
// EPI: 0=+bias, 1=+bias+relu, 2=*0.125 & (==0 -> NEGV), 3=none.
// WMODE bit0: write f32 C; bit1: write split Chi/Clo.
template<int EPI, int TB, int WMODE>
__global__ __launch_bounds__(128)
void gemm_bf16(const __nv_bfloat16* __restrict__ Agh, const __nv_bfloat16* __restrict__ Agl,
               const __nv_bfloat16* __restrict__ Bgh, const __nv_bfloat16* __restrict__ Bgl,
               const float* __restrict__ bias,
               float* __restrict__ C, __nv_bfloat16* __restrict__ Chi,
               __nv_bfloat16* __restrict__ Clo,
               int M, int N, int K, int lda, int ldb, int ldc,
               int zdiv, long long sA1, long long sA2, long long sB1, long long sB2,
               long long sC1, long long sC2, long long sBias) {
    constexpr int BROWS = TB ? 64 : 32;
    constexpr int BSTR  = TB ? 40 : 72;
    __shared__ __align__(16) __nv_bfloat16 sAh[2][64][40], sAl[2][64][40];
    __shared__ __align__(16) __nv_bfloat16 sBh[2][BROWS][BSTR], sBl[2][BROWS][BSTR];

    int z = blockIdx.z, z1 = z / zdiv, z2 = z % zdiv;
    const __nv_bfloat16* Abh = Agh + z1*sA1 + z2*sA2;
    const __nv_bfloat16* Abl = Agl + z1*sA1 + z2*sA2;
    const __nv_bfloat16* Bbh = Bgh + z1*sB1 + z2*sB2;
    const __nv_bfloat16* Bbl = Bgl + z1*sB1 + z2*sB2;
    long long coff = z1*sC1 + z2*sC2;

    int m0 = blockIdx.y * 64, n0 = blockIdx.x * 64;
    int tid = threadIdx.x, lane = tid & 31, wid = tid >> 5;
    int wm = wid & 1, wn = wid >> 1;
    int gid = lane >> 2, tig = lane & 3;

    auto load_stage = [&](int st, int kt) {
        int k0 = kt * 32;
        {
            int r = tid >> 2, cb = (tid & 3) * 8;
            cpa(&sAh[st][r   ][cb], Abh + (size_t)(m0 + r   )*lda + k0 + cb);
            cpa(&sAh[st][r+32][cb], Abh + (size_t)(m0 + r+32)*lda + k0 + cb);
            cpa(&sAl[st][r   ][cb], Abl + (size_t)(m0 + r   )*lda + k0 + cb);
            cpa(&sAl[st][r+32][cb], Abl + (size_t)(m0 + r+32)*lda + k0 + cb);
        }
        if (TB) {
            int r = tid >> 2, cb = (tid & 3) * 8;
            cpa(&sBh[st][r   ][cb], Bbh + (size_t)(n0 + r   )*ldb + k0 + cb);
            cpa(&sBh[st][r+32][cb], Bbh + (size_t)(n0 + r+32)*ldb + k0 + cb);
            cpa(&sBl[st][r   ][cb], Bbl + (size_t)(n0 + r   )*ldb + k0 + cb);
            cpa(&sBl[st][r+32][cb], Bbl + (size_t)(n0 + r+32)*ldb + k0 + cb);
        } else {
            int r = tid >> 3, cb = (tid & 7) * 8;
            cpa(&sBh[st][r   ][cb], Bbh + (size_t)(k0 + r   )*ldb + n0 + cb);
            cpa(&sBh[st][r+16][cb], Bbh + (size_t)(k0 + r+16)*ldb + n0 + cb);
            cpa(&sBl[st][r   ][cb], Bbl + (size_t)(k0 + r   )*ldb + n0 + cb);
            cpa(&sBl[st][r+16][cb], Bbl + (size_t)(k0 + r+16)*ldb + n0 + cb);
        }
    };

    float acc[2][4][4] = {};
    const int KT = K / 32;

    load_stage(0, 0);
    asm volatile("cp.async.commit_group;\n");

    for (int kt = 0; kt < KT; kt++) {
        int st = kt & 1;
        if (kt + 1 < KT) {
            load_stage(st ^ 1, kt + 1);
            asm volatile("cp.async.commit_group;\n");
            asm volatile("cp.async.wait_group 1;\n");
        } else {
            asm volatile("cp.async.wait_group 0;\n");
        }
        __syncthreads();

#pragma unroll
        for (int kk = 0; kk < 2; kk++) {
            int kc = kk * 16 + ((lane >> 4) << 3);
            uint32_t ah[2][4], al[2][4], bh[4][2], bl[4][2];
#pragma unroll
            for (int mi = 0; mi < 2; mi++) {
                const __nv_bfloat16* pa = &sAh[st][wm*32 + mi*16 + (lane & 15)][kc];
                ldsm4(ah[mi][0], ah[mi][1], ah[mi][2], ah[mi][3], pa);
                const __nv_bfloat16* pl = &sAl[st][wm*32 + mi*16 + (lane & 15)][kc];
                ldsm4(al[mi][0], al[mi][1], al[mi][2], al[mi][3], pl);
            }
#pragma unroll
            for (int ng = 0; ng < 2; ng++) {
                uint32_t r0, r1, r2, r3;
                if (TB) {
                    const __nv_bfloat16* pb = &sBh[st][wn*32 + ng*16 + (lane & 15)][kc];
                    ldsm4(r0, r1, r2, r3, pb);
                    bh[ng*2  ][0] = r0; bh[ng*2  ][1] = r2;
                    bh[ng*2+1][0] = r1; bh[ng*2+1][1] = r3;
                    const __nv_bfloat16* pbl = &sBl[st][wn*32 + ng*16 + (lane & 15)][kc];
                    ldsm4(r0, r1, r2, r3, pbl);
                    bl[ng*2  ][0] = r0; bl[ng*2  ][1] = r2;
                    bl[ng*2+1][0] = r1; bl[ng*2+1][1] = r3;
                } else {
                    int rr = kk*16 + ((lane >> 4) << 3) + (lane & 7);
                    int cc = wn*32 + ng*16 + (((lane >> 3) & 1) << 3);
                    ldsm4t(r0, r1, r2, r3, &sBh[st][rr][cc]);
                    bh[ng*2  ][0] = r0; bh[ng*2  ][1] = r2;
                    bh[ng*2+1][0] = r1; bh[ng*2+1][1] = r3;
                    ldsm4t(r0, r1, r2, r3, &sBl[st][rr][cc]);
                    bl[ng*2  ][0] = r0; bl[ng*2  ][1] = r2;
                    bl[ng*2+1][0] = r1; bl[ng*2+1][1] = r3;
                }
            }
            // hh, then hl, then lh  (keeps same-acc RAW chains 8 apart)
#pragma unroll
            for (int mi = 0; mi < 2; mi++)
#pragma unroll
                for (int ni = 0; ni < 4; ni++) mma_bf16(acc[mi][ni], ah[mi], bh[ni]);
#pragma unroll
            for (int mi = 0; mi < 2; mi++)
#pragma unroll
                for (int ni = 0; ni < 4; ni++) mma_bf16(acc[mi][ni], ah[mi], bl[ni]);
#pragma unroll
            for (int mi = 0; mi < 2; mi++)
#pragma unroll
                for (int ni = 0; ni < 4; ni++) mma_bf16(acc[mi][ni], al[mi], bh[ni]);
        }
        __syncthreads();
    }

    const float* biasb = (EPI <= 1) ? bias + (long long)z * sBias : nullptr;
#pragma unroll
    for (int mi = 0; mi < 2; mi++)
#pragma unroll
        for (int ni = 0; ni < 4; ni++) {
            int row = m0 + wm*32 + mi*16 + gid;
            int col = n0 + wn*32 + ni*8 + tig*2;
#pragma unroll
            for (int e2 = 0; e2 < 4; e2++) {
                int r  = row + (e2 >> 1)*8;
                int cc = col + (e2 & 1);
                float v = acc[mi][ni][e2];
                if (EPI == 0 || EPI == 1) v += biasb[cc];
                if (EPI == 1) v = fmaxf(v, 0.f);
                if (EPI == 2) { v *= 0.125f; if (v == 0.f) v = NEGV; }
                size_t idx = coff + (size_t)r*ldc + cc;
                if (WMODE & 1) C[idx] = v;
                if (WMODE & 2) {
                    __nv_bfloat16 h = __float2bfloat16(v);
                    Chi[idx] = h;
                    Clo[idx] = __float2bfloat16(v - __bfloat162float(h));
                }
            }
        }
}

// ---------------- row softmax over 512 -> split bf16 ----------------
__global__ void softmax512(const float* __restrict__ s, __nv_bfloat16* __restrict__ phi,
                           __nv_bfloat16* __restrict__ plo) {
    size_t row = blockIdx.x;
    const float* p = s + row * Sz;
    int tid = threadIdx.x;                 // 128
    float4 v = *(const float4*)&p[tid*4];
    float mx = fmaxf(fmaxf(v.x, v.y), fmaxf(v.z, v.w));
#pragma unroll
    for (int o = 16; o; o >>= 1) mx = fmaxf(mx, __shfl_xor_sync(0xffffffffu, mx, o));
    __shared__ float sm[4];
    if ((tid & 31) == 0) sm[tid >> 5] = mx;
    __syncthreads();
    mx = fmaxf(fmaxf(sm[0], sm[1]), fmaxf(sm[2], sm[3]));
    v.x = expf(v.x - mx); v.y = expf(v.y - mx);
    v.z = expf(v.z - mx); v.w = expf(v.w - mx);
    float sum = v.x + v.y + v.z + v.w;
#pragma unroll
    for (int o = 16; o; o >>= 1) sum += __shfl_xor_sync(0xffffffffu, sum, o);
    __shared__ float ss[4];
    if ((tid & 31) == 0) ss[tid >> 5] = sum;
    __syncthreads();
    sum = ss[0] + ss[1] + ss[2] + ss[3];
    float inv = 1.f / sum;
    float vv[4] = {v.x*inv, v.y*inv, v.z*inv, v.w*inv};
    __nv_bfloat16 hh[4], ll[4];
#pragma unroll
    for (int j = 0; j < 4; j++) {
        hh[j] = __float2bfloat16(vv[j]);
        ll[j] = __float2bfloat16(vv[j] - __bfloat162float(hh[j]));
    }
    *(uint2*)&phi[row*Sz + tid*4] = *(uint2*)hh;
    *(uint2*)&plo[row*Sz + tid*4] = *(uint2*)ll;
}

// ---------------- out = LayerNorm(a + res) (+ optional split) ----------------
template<int SPLIT>
__global__ void add_ln(const float* __restrict__ a, const float* __restrict__ res,
                       const float* __restrict__ g, const float* __restrict__ beta,
                       float* __restrict__ out, __nv_bfloat16* __restrict__ ohi,
                       __nv_bfloat16* __restrict__ olo) {
    size_t row = blockIdx.x;
    int tid = threadIdx.x;
    int c = tid * 4;
    float4 av = *(const float4*)&a[row*Dm + c];
    float4 rv = *(const float4*)&res[row*Dm + c];
    float4 x;
    x.x = av.x + rv.x; x.y = av.y + rv.y; x.z = av.z + rv.z; x.w = av.w + rv.w;
    float s  = x.x + x.y + x.z + x.w;
    float s2 = x.x*x.x + x.y*x.y + x.z*x.z + x.w*x.w;
#pragma unroll
    for (int o = 16; o; o >>= 1) {
        s  += __shfl_xor_sync(0xffffffffu, s,  o);
        s2 += __shfl_xor_sync(0xffffffffu, s2, o);
    }
    __shared__ float sm[4], sq[4];
    if ((tid & 31) == 0) { sm[tid>>5] = s; sq[tid>>5] = s2; }
    __syncthreads();
    s  = sm[0] + sm[1] + sm[2] + sm[3];
    s2 = sq[0] + sq[1] + sq[2] + sq[3];
    float mean = s * (1.f/Dm);
    float var  = s2 * (1.f/Dm) - mean*mean;
    float inv  = rsqrtf(var + 1e-5f);
    float4 gv = *(const float4*)&g[c];
    float4 bv = *(const float4*)&beta[c];
    float y[4];
    y[0] = (x.x - mean)*inv*gv.x + bv.x;
    y[1] = (x.y - mean)*inv*gv.y + bv.y;
    y[2] = (x.z - mean)*inv*gv.z + bv.z;
    y[3] = (x.w - mean)*inv*gv.w + bv.w;
    *(float4*)&out[row*Dm + c] = *(float4*)y;
    if (SPLIT) {
        __nv_bfloat16 hh[4], ll[4];
#pragma unroll
        for (int j = 0; j < 4; j++) {
            hh[j] = __float2bfloat16(y[j]);
            ll[j] = __float2bfloat16(y[j] - __bfloat162float(hh[j]));
        }
        *(uint2*)&ohi[row*Dm + c] = *(uint2*)hh;
        *(uint2*)&olo[row*Dm + c] = *(uint2*)ll;
    }
}

// ---------------- decoder cross-attention (Sq=1, f32) ----------------
__global__ void cross_attn(const float* __restrict__ q, const float* __restrict__ k,
                           const float* __restrict__ v, float* __restrict__ o) {
    int h = blockIdx.x, b = blockIdx.y;
    __shared__ float qv[64];
    __shared__ float p[512];
    __shared__ float red[8];
    int tid = threadIdx.x;
    if (tid < 64) qv[tid] = q[b*Dm + h*DKh + tid];
    __syncthreads();
    float sc[2];
    float lmax = -INFINITY;
#pragma unroll
    for (int it = 0; it < 2; it++) {
        int j = tid + it*256;
        const float* kp = &k[(size_t)(b*Sz + j)*Dm + h*DKh];
        float s = 0.f;
#pragma unroll
        for (int c = 0; c < 64; c++) s += qv[c] * kp[c];
        s *= 0.125f;
        if (s == 0.f) s = NEGV;
        sc[it] = s;
        lmax = fmaxf(lmax, s);
    }
#pragma unroll
    for (int off = 16; off; off >>= 1) lmax = fmaxf(lmax, __shfl_xor_sync(0xffffffffu, lmax, off));
    if ((tid & 31) == 0) red[tid >> 5] = lmax;
    __syncthreads();
    float mx = red[0];
#pragma unroll
    for (int w = 1; w < 8; w++) mx = fmaxf(mx, red[w]);
    __syncthreads();
    float lsum = 0.f;
#pragma unroll
    for (int it = 0; it < 2; it++) {
        float e = expf(sc[it] - mx);
        p[tid + it*256] = e;
        lsum += e;
    }
#pragma unroll
    for (int off = 16; off; off >>= 1) lsum += __shfl_xor_sync(0xffffffffu, lsum, off);
    if ((tid & 31) == 0) red[tid >> 5] = lsum;
    __syncthreads();
    float sum = red[0] + red[1] + red[2] + red[3] + red[4] + red[5] + red[6] + red[7];
    float inv = 1.f / sum;
    int warp = tid >> 5, lane = tid & 31;
#pragma unroll
    for (int dd = 0; dd < 8; dd++) {
        int d = warp*8 + dd;
        float acc = 0.f;
        for (int j = lane; j < Sz; j += 32)
            acc += p[j] * v[(size_t)(b*Sz + j)*Dm + h*DKh + d];
#pragma unroll
        for (int off = 16; off; off >>= 1) acc += __shfl_xor_sync(0xffffffffu, acc, off);
        if (lane == 0) o[b*Dm + h*DKh + d] = acc * inv;
    }
}

// ---------------- tiny-M (M=8) GEMM for decoder ----------------
__global__ void gemm8(const float* __restrict__ A, const float* __restrict__ W,
                      const float* __restrict__ bias, float* __restrict__ C,
                      int K, int N, int relu) {
    int col = blockIdx.x*blockDim.x + threadIdx.x;
    if (col >= N) return;
    float acc[8] = {};
    for (int k = 0; k < K; k++) {
        float wv = W[(size_t)k*N + col];
#pragma unroll
        for (int r = 0; r < 8; r++) acc[r] += A[r*K + k] * wv;
    }
    float bv = bias[col];
#pragma unroll
    for (int r = 0; r < 8; r++) {
        float val = acc[r] + bv;
        if (relu) val = fmaxf(val, 0.f);
        C[r*N + col] = val;
    }
}

// ---------------- host orchestration ----------------
extern "C" void kernel_launch(void* const* d_in, const int* in_sizes, int n_in,
                              void* d_out, int out_size) {
    const int*   x        = (const int*)d_in[0];
    const int*   tgt      = (const int*)d_in[1];
    const float* in_emb   = (const float*)d_in[2];
    const float* out_emb  = (const float*)d_in[3];
    const float* enc_qkv_w = (const float*)d_in[4];
    const float* enc_qkv_b = (const float*)d_in[5];
    const float* enc_ln1_g = (const float*)d_in[6];
    const float* enc_ln1_b = (const float*)d_in[7];
    const float* enc_ffn1_w = (const float*)d_in[8];
    const float* enc_ffn1_b = (const float*)d_in[9];
    const float* enc_ffn2_w = (const float*)d_in[10];
    const float* enc_ffn2_b = (const float*)d_in[11];
    const float* enc_ln2_g = (const float*)d_in[12];
    const float* enc_ln2_b = (const float*)d_in[13];
    const float* dec_qkv1_w = (const float*)d_in[14];
    const float* dec_qkv1_b = (const float*)d_in[15];
    const float* dec_ln1_g = (const float*)d_in[16];
    const float* dec_ln1_b = (const float*)d_in[17];
    const float* dec_qkv2_w = (const float*)d_in[18];
    const float* dec_qkv2_b = (const float*)d_in[19];
    const float* dec_ln2_g = (const float*)d_in[20];
    const float* dec_ln2_b = (const float*)d_in[21];
    const float* dec_ffn1_w = (const float*)d_in[22];
    const float* dec_ffn1_b = (const float*)d_in[23];
    const float* dec_ffn2_w = (const float*)d_in[24];
    const float* dec_ffn2_b = (const float*)d_in[25];
    const float* dec_ln3_g = (const float*)d_in[26];
    const float* dec_ln3_b = (const float*)d_in[27];
    const float* out_w = (const float*)d_in[28];
    const float* out_b = (const float*)d_in[29];

    float *e, *sc, *attn, *tbuf, *dbuf, *dq, *dt, *dh, *kvf;
    __nv_bfloat16 *ehi, *elo, *qkvh, *qkvl, *schi, *sclo, *hhi, *hlo;
    __nv_bfloat16 *wqkvh, *wqkvl, *wf1h, *wf1l, *wf2h, *wf2l, *wd2h, *wd2l;
    cudaGetSymbolAddress((void**)&e,    g_e);
    cudaGetSymbolAddress((void**)&ehi,  g_ehi);
    cudaGetSymbolAddress((void**)&elo,  g_elo);
    cudaGetSymbolAddress((void**)&qkvh, g_qkvh);
    cudaGetSymbolAddress((void**)&qkvl, g_qkvl);
    cudaGetSymbolAddress((void**)&kvf,  g_kvf);
    cudaGetSymbolAddress((void**)&sc,   g_sc);
    cudaGetSymbolAddress((void**)&schi, g_schi);
    cudaGetSymbolAddress((void**)&sclo, g_sclo);
    cudaGetSymbolAddress((void**)&attn, g_attn);
    cudaGetSymbolAddress((void**)&hhi,  g_hhi);
    cudaGetSymbolAddress((void**)&hlo,  g_hlo);
    cudaGetSymbolAddress((void**)&tbuf, g_t);
    cudaGetSymbolAddress((void**)&dbuf, g_d);
    cudaGetSymbolAddress((void**)&dq,   g_dq);
    cudaGetSymbolAddress((void**)&dt,   g_dt);
    cudaGetSymbolAddress((void**)&dh,   g_dh);
    cudaGetSymbolAddress((void**)&wqkvh, g_wqkvh);
    cudaGetSymbolAddress((void**)&wqkvl, g_wqkvl);
    cudaGetSymbolAddress((void**)&wf1h, g_wf1h);
    cudaGetSymbolAddress((void**)&wf1l, g_wf1l);
    cudaGetSymbolAddress((void**)&wf2h, g_wf2h);
    cudaGetSymbolAddress((void**)&wf2l, g_wf2l);
    cudaGetSymbolAddress((void**)&wd2h, g_wd2h);
    cudaGetSymbolAddress((void**)&wd2l, g_wd2l);

    const int M = Bz*Sz;            // 4096
    const long long DD = (long long)Dm*Dm;
    const long long MD = (long long)M*Dm;
    const long long SS = (long long)Sz*Sz;
    const long long SDm = (long long)Sz*Dm;

    // ---- split weights once per launch ----
    {
        int n1 = Lz*3*Dm*Dm;
        splitk<<<(n1+255)/256, 256>>>(enc_qkv_w, wqkvh, wqkvl, n1);
        int n2 = Lz*Dm*DFFz;
        splitk<<<(n2+255)/256, 256>>>(enc_ffn1_w, wf1h, wf1l, n2);
        splitk<<<(n2+255)/256, 256>>>(enc_ffn2_w, wf2h, wf2l, n2);
        splitk<<<(n1+255)/256, 256>>>(dec_qkv2_w, wd2h, wd2l, n1);
    }

    // ---------------- encoder ----------------
    embed_enc<<<(Bz*Sz*Dm + 255)/256, 256>>>(x, in_emb, e, ehi, elo);
    for (int i = 0; i < Lz; i++) {
        // fused QKV: z=3 weight matrices, split output
        gemm_bf16<0,0,2><<<dim3(Dm/64, M/64, 3), 128>>>(
            ehi, elo, wqkvh + (size_t)i*3*DD, wqkvl + (size_t)i*3*DD,
            enc_qkv_b + (size_t)i*3*Dm, nullptr, qkvh, qkvl,
            M, Dm, Dm, Dm, Dm, Dm,
            1, 0, 0, DD, 0, MD, 0, Dm);
        // scores: per (b,h), S = Q K^T / 8 + quirky mask (f32 out)
        gemm_bf16<2,1,1><<<dim3(Sz/64, Sz/64, Bz*Hn), 128>>>(
            qkvh, qkvl, qkvh + MD, qkvl + MD, nullptr, sc, nullptr, nullptr,
            Sz, Sz, DKh, Dm, Dm, Sz,
            Hn, SDm, DKh, SDm, DKh, (long long)Hn*SS, SS, 0);
        softmax512<<<Bz*Hn*Sz, 128>>>(sc, schi, sclo);
        // PV: per (b,h), O = P V (f32 out)
        gemm_bf16<3,0,1><<<dim3(DKh/64, Sz/64, Bz*Hn), 128>>>(
            schi, sclo, qkvh + 2*MD, qkvl + 2*MD, nullptr, attn, nullptr, nullptr,
            Sz, DKh, Sz, Sz, Dm, Dm,
            Hn, (long long)Hn*SS, SS, SDm, DKh, SDm, DKh, 0);
        add_ln<1><<<M, 128>>>(attn, e, enc_ln1_g + i*Dm, enc_ln1_b + i*Dm, e, ehi, elo);
        // FFN1 (+relu), split-only out
        gemm_bf16<1,0,2><<<dim3(DFFz/64, M/64, 1), 128>>>(
            ehi, elo, wf1h + (size_t)i*Dm*DFFz, wf1l + (size_t)i*Dm*DFFz,
            enc_ffn1_b + (size_t)i*DFFz, nullptr, hhi, hlo,
            M, DFFz, Dm, Dm, DFFz, DFFz,
            1, 0, 0, 0, 0, 0, 0, 0);
        // FFN2 (f32 out)
        gemm_bf16<0,0,1><<<dim3(Dm/64, M/64, 1), 128>>>(
            hhi, hlo, wf2h + (size_t)i*DFFz*Dm, wf2l + (size_t)i*DFFz*Dm,
            enc_ffn2_b + (size_t)i*Dm, tbuf, nullptr, nullptr,
            M, Dm, DFFz, DFFz, Dm, Dm,
            1, 0, 0, 0, 0, 0, 0, 0);
        add_ln<1><<<M, 128>>>(tbuf, e, enc_ln2_g + i*Dm, enc_ln2_b + i*Dm, e, ehi, elo);
    }

    // ---------------- decoder (seq len 1; self-attn == V projection) --------
    embed_dec<<<(Bz*Dm + 255)/256, 256>>>(tgt, out_emb, dbuf);
    for (int i = 0; i < Lz; i++) {
        gemm8<<<(Dm+127)/128, 128>>>(dbuf, dec_qkv1_w + (size_t)(i*3+2)*DD, dec_qkv1_b + (i*3+2)*Dm, dt, Dm, Dm, 0);
        add_ln<0><<<Bz, 128>>>(dt, dbuf, dec_ln1_g + i*Dm, dec_ln1_b + i*Dm, dbuf, nullptr, nullptr);
        // cross-attn: q from decoder state; K,V projections of encoder output (z=2)
        gemm8<<<(Dm+127)/128, 128>>>(dbuf, dec_qkv2_w + (size_t)(i*3+0)*DD, dec_qkv2_b + (i*3+0)*Dm, dq, Dm, Dm, 0);
        gemm_bf16<0,0,1><<<dim3(Dm/64, M/64, 2), 128>>>(
            ehi, elo, wd2h + (size_t)(i*3+1)*DD, wd2l + (size_t)(i*3+1)*DD,
            dec_qkv2_b + (size_t)(i*3+1)*Dm, kvf, nullptr, nullptr,
            M, Dm, Dm, Dm, Dm, Dm,
            1, 0, 0, DD, 0, MD, 0, Dm);
        cross_attn<<<dim3(Hn, Bz), 256>>>(dq, kvf /*K*/, kvf + MD /*V*/, dt);
        add_ln<0><<<Bz, 128>>>(dt, dbuf, dec_ln2_g + i*Dm, dec_ln2_b + i*Dm, dbuf, nullptr, nullptr);
        gemm8<<<(DFFz+127)/128, 128>>>(dbuf, dec_ffn1_w + (size_t)i*Dm*DFFz, dec_ffn1_b + i*DFFz, dh, Dm, DFFz, 1);
        gemm8<<<(Dm+127)/128, 128>>>(dh, dec_ffn2_w + (size_t)i*DFFz*Dm, dec_ffn2_b + i*Dm, dt, DFFz, Dm, 0);
        add_ln<0><<<Bz, 128>>>(dt, dbuf, dec_ln3_g + i*Dm, dec_ln3_b + i*Dm, dbuf, nullptr, nullptr);
    }

    // output projection -> d_out [8,1,1000]
    gemm8<<<(OUTz+127)/128, 128>>>(dbuf, out_w, out_b, (float*)d_out, Dm, OUTz, 0);
    (void)in_sizes; (void)n_in; (void)out_size;
}